// round 16
// baseline (speedup 1.0000x reference)
#include <cuda_runtime.h>
#include <cuda_bf16.h>
#include <cstdint>

#define B_DIM 2
#define E_DIM 1024
#define C_DIM 128
#define R_REL 32

#define MT 32          // s rows per block
#define NT 32          // o cols per tile (2 tiles per block)
#define GSTRIDE 136    // bf16 per smem operand row (128 + 8): LDSM-safe
#define GS 36          // floats per smem G row (32 + 4): float4-safe

// Dynamic smem (bytes) — round-9/13 proven non-aliased layout:
//   sA: [2][2][MT][GSTRIDE] bf16   A tiles (batch, hi/lo)   34816
//   sB: [2][2][NT][GSTRIDE] bf16   B tiles (batch, hi/lo)   34816
//   sG: [2][MT][GS] float          G tile                    9216
#define SA_OFF 0
#define SB_OFF 34816
#define SG_OFF 69632
#define SMEM_BYTES 78848

__device__ __forceinline__ uint32_t ldsm_addr(const __nv_bfloat16* p) {
    return (uint32_t)__cvta_generic_to_shared(p);
}

// Fill one operand region (32 rows starting at grow0) with hi/lo split.
__device__ __forceinline__ void fill_split(const float* __restrict__ x,
                                           __nv_bfloat16* dst, int grow0, int tid) {
    const int row  = tid >> 3;        // 0..31
    const int col4 = tid & 7;         // 0..7
    #pragma unroll
    for (int b = 0; b < 2; b++) {
        const float4* src = (const float4*)(x + ((size_t)b * E_DIM + grow0 + row) * C_DIM);
        __nv_bfloat16* dhi = dst + ((b * 2 + 0) * MT + row) * GSTRIDE;
        __nv_bfloat16* dlo = dst + ((b * 2 + 1) * MT + row) * GSTRIDE;
        #pragma unroll
        for (int i = 0; i < 4; i++) {
            const int c4 = col4 + i * 8;
            float4 v = src[c4];
            __nv_bfloat162 h0 = __floats2bfloat162_rn(v.x, v.y);
            __nv_bfloat162 h1 = __floats2bfloat162_rn(v.z, v.w);
            float lx = v.x - __bfloat162float(__low2bfloat16(h0));
            float ly = v.y - __bfloat162float(__high2bfloat16(h0));
            float lz = v.z - __bfloat162float(__low2bfloat16(h1));
            float lw = v.w - __bfloat162float(__high2bfloat16(h1));
            ((__nv_bfloat162*)(dhi + c4 * 4))[0] = h0;
            ((__nv_bfloat162*)(dhi + c4 * 4))[1] = h1;
            ((__nv_bfloat162*)(dlo + c4 * 4))[0] = __floats2bfloat162_rn(lx, ly);
            ((__nv_bfloat162*)(dlo + c4 * 4))[1] = __floats2bfloat162_rn(lz, lw);
        }
    }
}

// MMA: warp tile 16m x 16n, round-7 validated fragment geometry. acc[2][4].
__device__ __forceinline__ void mma_tile(const __nv_bfloat16* sA, const __nv_bfloat16* sB,
                                         int wb, int wm, int wn, int lane,
                                         float acc[2][4]) {
    #pragma unroll
    for (int j = 0; j < 2; j++)
        #pragma unroll
        for (int k = 0; k < 4; k++) acc[j][k] = 0.f;

    const int paT[3] = {0, 1, 0};
    const int pbT[3] = {0, 0, 1};

    #pragma unroll
    for (int pass = 0; pass < 3; pass++) {
        const __nv_bfloat16* Ab = sA + ((wb * 2 + paT[pass]) * MT) * GSTRIDE;
        const __nv_bfloat16* Bb = sB + ((wb * 2 + pbT[pass]) * NT) * GSTRIDE;
        #pragma unroll
        for (int ks = 0; ks < 8; ks++) {
            uint32_t a[4];
            {
                int r = wm * 16 + ((lane >> 3) & 1) * 8 + (lane & 7);
                int c = ks * 16 + (lane >> 4) * 8;
                uint32_t addr = ldsm_addr(Ab + r * GSTRIDE + c);
                asm volatile("ldmatrix.sync.aligned.m8n8.x4.shared.b16 {%0,%1,%2,%3}, [%4];"
                             : "=r"(a[0]), "=r"(a[1]), "=r"(a[2]), "=r"(a[3]) : "r"(addr));
            }
            uint32_t bf[4];
            {
                int r = wn * 16 + ((lane >> 4) & 1) * 8 + (lane & 7);
                int c = ks * 16 + ((lane >> 3) & 1) * 8;
                uint32_t addr = ldsm_addr(Bb + r * GSTRIDE + c);
                asm volatile("ldmatrix.sync.aligned.m8n8.x4.shared.b16 {%0,%1,%2,%3}, [%4];"
                             : "=r"(bf[0]), "=r"(bf[1]), "=r"(bf[2]), "=r"(bf[3]) : "r"(addr));
            }
            #pragma unroll
            for (int nt = 0; nt < 2; nt++) {
                asm volatile(
                    "mma.sync.aligned.m16n8k16.row.col.f32.bf16.bf16.f32 "
                    "{%0,%1,%2,%3}, {%4,%5,%6,%7}, {%8,%9}, {%0,%1,%2,%3};"
                    : "+f"(acc[nt][0]), "+f"(acc[nt][1]), "+f"(acc[nt][2]), "+f"(acc[nt][3])
                    : "r"(a[0]), "r"(a[1]), "r"(a[2]), "r"(a[3]),
                      "r"(bf[nt * 2 + 0]), "r"(bf[nt * 2 + 1]));
            }
        }
    }
}

__device__ __forceinline__ void store_G(float* sG, const float acc[2][4],
                                        int wb, int wm, int wn, int lane) {
    #pragma unroll
    for (int nt = 0; nt < 2; nt++) {
        int m = wm * 16 + (lane >> 2);
        int n = wn * 16 + nt * 8 + (lane & 3) * 2;
        float* g = sG + (wb * MT + m) * GS + n;
        *(float2*)g            = make_float2(acc[nt][0], acc[nt][1]);
        *(float2*)(g + 8 * GS) = make_float2(acc[nt][2], acc[nt][3]);
    }
}

__global__ __launch_bounds__(256, 2) void fused_kernel(const float* __restrict__ x,
                                                       const float4* __restrict__ Rrel,
                                                       float4* __restrict__ out) {
    extern __shared__ char smem[];
    __nv_bfloat16* sA = (__nv_bfloat16*)(smem + SA_OFF);
    __nv_bfloat16* sB = (__nv_bfloat16*)(smem + SB_OFF);
    float*         sG = (float*)(smem + SG_OFF);

    // 512 blocks: s_idx = bid>>4 (32), o_pair = bid&15 (16 pairs of o tiles).
    const int s0  = (blockIdx.x >> 4) * MT;
    const int o0a = (blockIdx.x & 15) * (2 * NT);    // tile 0
    const int o0b = o0a + NT;                        // tile 1

    const int tid  = threadIdx.x;
    const int lane = tid & 31;
    const int wid  = tid >> 5;
    const int wb = wid >> 2;
    const int wm = (wid >> 1) & 1;
    const int wn = wid & 1;

    // Epilogue thread mapping.
    const int o4 = tid & 7;
    const int si = tid >> 3;
    const int E4 = E_DIM / 4;
    const int sg = s0 + si;
    const size_t rstep = (size_t)E_DIM * E4;

    // ---- Phase 0: L2 prefetch of BOTH tiles' R set (32r x 32s x 256B) ----
    {
        const int ps = tid & 31;
        #pragma unroll
        for (int i = 0; i < 4; i++) {
            int r = (tid >> 5) + i * 8;       // 0..31
            const float* p = (const float*)Rrel +
                ((size_t)r * E_DIM + (s0 + ps)) * E_DIM + o0a;
            asm volatile("prefetch.global.L2 [%0];" :: "l"(p));
            asm volatile("prefetch.global.L2 [%0];" :: "l"(p + 32));
        }
    }

    // ---- Fill sA (shared by both tiles) + sB(tile 0) ----
    fill_split(x, sA, s0, tid);
    fill_split(x, sB, o0a, tid);
    __syncthreads();

    // ---- MMA tile 0 ----
    float acc[2][4];
    mma_tile(sA, sB, wb, wm, wn, lane, acc);
    __syncthreads();                 // all warps done reading sB

    // ---- store G(tile0); refill sB with tile 1 operands ----
    store_G(sG, acc, wb, wm, wn, lane);
    fill_split(x, sB, o0b, tid);     // x is L2-resident; fast
    __syncthreads();                 // sG + sB ready

    // ---- Epilogue(tile 0) overlapped with MMA(tile 1) ----
    {
        const int o4g = (o0a >> 2) + o4;
        const size_t rbase = (size_t)sg * E4 + o4g;
        const size_t ob0   = ((size_t)sg * R_REL) * E4 + o4g;
        const size_t ob1   = (((size_t)E_DIM + sg) * R_REL) * E4 + o4g;

        // Issue chunk-0 R loads first: their DRAM latency hides under the MMA.
        float4 rv[8];
        #pragma unroll
        for (int rr = 0; rr < 8; rr++)
            rv[rr] = __ldcs(&Rrel[(size_t)rr * rstep + rbase]);

        // MMA for tile 1 while chunk-0 loads are in flight.
        mma_tile(sA, sB, wb, wm, wn, lane, acc);

        const float4 g0 = *(const float4*)(sG + (0 * MT + si) * GS + o4 * 4);
        const float4 g1 = *(const float4*)(sG + (1 * MT + si) * GS + o4 * 4);

        #pragma unroll
        for (int rr = 0; rr < 8; rr++) {
            float4 a, c;
            a.x = g0.x * rv[rr].x;  a.y = g0.y * rv[rr].y;
            a.z = g0.z * rv[rr].z;  a.w = g0.w * rv[rr].w;
            c.x = g1.x * rv[rr].x;  c.y = g1.y * rv[rr].y;
            c.z = g1.z * rv[rr].z;  c.w = g1.w * rv[rr].w;
            __stcs(&out[ob0 + (size_t)rr * E4], a);
            __stcs(&out[ob1 + (size_t)rr * E4], c);
        }
        #pragma unroll
        for (int rc = 8; rc < R_REL; rc += 8) {
            #pragma unroll
            for (int rr = 0; rr < 8; rr++)
                rv[rr] = __ldcs(&Rrel[(size_t)(rc + rr) * rstep + rbase]);
            #pragma unroll
            for (int rr = 0; rr < 8; rr++) {
                const int r = rc + rr;
                float4 a, c;
                a.x = g0.x * rv[rr].x;  a.y = g0.y * rv[rr].y;
                a.z = g0.z * rv[rr].z;  a.w = g0.w * rv[rr].w;
                c.x = g1.x * rv[rr].x;  c.y = g1.y * rv[rr].y;
                c.z = g1.z * rv[rr].z;  c.w = g1.w * rv[rr].w;
                __stcs(&out[ob0 + (size_t)r * E4], a);
                __stcs(&out[ob1 + (size_t)r * E4], c);
            }
        }
    }
    __syncthreads();                 // epilogue(t0) done reading sG

    // ---- store G(tile1); epilogue(tile 1) ----
    store_G(sG, acc, wb, wm, wn, lane);
    __syncthreads();

    {
        const int o4g = (o0b >> 2) + o4;
        const size_t rbase = (size_t)sg * E4 + o4g;
        const size_t ob0   = ((size_t)sg * R_REL) * E4 + o4g;
        const size_t ob1   = (((size_t)E_DIM + sg) * R_REL) * E4 + o4g;

        const float4 g0 = *(const float4*)(sG + (0 * MT + si) * GS + o4 * 4);
        const float4 g1 = *(const float4*)(sG + (1 * MT + si) * GS + o4 * 4);

        #pragma unroll
        for (int rc = 0; rc < R_REL; rc += 8) {
            float4 rv[8];
            #pragma unroll
            for (int rr = 0; rr < 8; rr++)
                rv[rr] = __ldcs(&Rrel[(size_t)(rc + rr) * rstep + rbase]);
            #pragma unroll
            for (int rr = 0; rr < 8; rr++) {
                const int r = rc + rr;
                float4 a, c;
                a.x = g0.x * rv[rr].x;  a.y = g0.y * rv[rr].y;
                a.z = g0.z * rv[rr].z;  a.w = g0.w * rv[rr].w;
                c.x = g1.x * rv[rr].x;  c.y = g1.y * rv[rr].y;
                c.z = g1.z * rv[rr].z;  c.w = g1.w * rv[rr].w;
                __stcs(&out[ob0 + (size_t)r * E4], a);
                __stcs(&out[ob1 + (size_t)r * E4], c);
            }
        }
    }
}

extern "C" void kernel_launch(void* const* d_in, const int* in_sizes, int n_in,
                              void* d_out, int out_size) {
    const float* x  = (const float*)d_in[0];   // (B, E, C) fp32
    const float* Rr = (const float*)d_in[1];   // (R_REL, E, E) fp32
    float* out      = (float*)d_out;           // (B, E, R_REL, E) fp32

    cudaFuncSetAttribute(fused_kernel,
                         cudaFuncAttributeMaxDynamicSharedMemorySize, SMEM_BYTES);

    fused_kernel<<<512, 256, SMEM_BYTES>>>(x, (const float4*)Rr, (float4*)out);

    (void)in_sizes; (void)n_in; (void)out_size;
}

// round 17
// speedup vs baseline: 1.0902x; 1.0902x over previous
#include <cuda_runtime.h>
#include <cuda_bf16.h>
#include <cstdint>

#define B_DIM 2
#define E_DIM 1024
#define C_DIM 128
#define R_REL 32

#define MT 32          // s rows per block
#define NT 32          // o cols per block
#define GSTRIDE 136    // bf16 per smem operand row (128 + 8): 272B, LDSM-safe
#define GS 36          // floats per smem G row (32 + 4): 144B, float4-safe

// Dynamic smem layout (bytes) — round-13 proven layout:
//   sA: [2][2][MT][GSTRIDE] bf16   A tiles (batch, hi/lo)      34816
//   sB: [2][2][NT][GSTRIDE] bf16   B tiles (batch, hi/lo)      34816
//   sG: [2][MT][GS] float          G tiles                      9216
#define SA_OFF 0
#define SB_OFF 34816
#define SG_OFF 69632
#define SMEM_BYTES 78848

__device__ __forceinline__ uint32_t ldsm_addr(const __nv_bfloat16* p) {
    return (uint32_t)__cvta_generic_to_shared(p);
}

__global__ __launch_bounds__(256, 2) void fused_kernel(const float* __restrict__ x,
                                                       const float4* __restrict__ Rrel,
                                                       float4* __restrict__ out) {
    extern __shared__ char smem[];
    __nv_bfloat16* sA = (__nv_bfloat16*)(smem + SA_OFF);
    __nv_bfloat16* sB = (__nv_bfloat16*)(smem + SB_OFF);
    float*         sG = (float*)(smem + SG_OFF);

    const int o0 = blockIdx.x * NT;
    const int s0 = blockIdx.y * MT;
    const int tid  = threadIdx.x;
    const int lane = tid & 31;
    const int wid  = tid >> 5;

    // Prefetch lane mapping: one 128B line per thread per 8-r chunk.
    const int pr = tid >> 5;          // 0..7 (r within chunk)
    const int ps = tid & 31;          // 0..31 (s row)
    const float* pfbase = (const float*)Rrel +
        ((size_t)pr * E_DIM + (s0 + ps)) * E_DIM + o0;
    const size_t pfstride = (size_t)8 * E_DIM * E_DIM;   // +8 r

    // ---------------- Phase 0: prefetch ONLY chunk 0 ------------------------
    // Consumed immediately after the MMA -> cannot be evicted by the output
    // stream. Later chunks are prefetched inside the epilogue at one-chunk
    // distance (bulk up-front prefetch gets evicted by ~114MB of out flowing
    // through L2 during a block's lifetime, doubling R DRAM traffic).
    asm volatile("prefetch.global.L2 [%0];" :: "l"(pfbase));

    // ---------------- Phase 1: load x rows, split hi/lo into smem ----------
    {
        const int row  = tid >> 3;
        const int col4 = tid & 7;
        #pragma unroll
        for (int reg = 0; reg < 2; reg++) {          // 0 = A (s rows), 1 = B (o rows)
            const int grow = (reg ? o0 : s0) + row;
            __nv_bfloat16* dst = reg ? sB : sA;
            #pragma unroll
            for (int b = 0; b < 2; b++) {
                const float4* src = (const float4*)(x + ((size_t)b * E_DIM + grow) * C_DIM);
                __nv_bfloat16* dhi = dst + ((b * 2 + 0) * MT + row) * GSTRIDE;
                __nv_bfloat16* dlo = dst + ((b * 2 + 1) * MT + row) * GSTRIDE;
                #pragma unroll
                for (int i = 0; i < 4; i++) {
                    const int c4 = col4 + i * 8;      // 0..31 float4 cols
                    float4 v = src[c4];
                    __nv_bfloat162 h0 = __floats2bfloat162_rn(v.x, v.y);
                    __nv_bfloat162 h1 = __floats2bfloat162_rn(v.z, v.w);
                    float lx = v.x - __bfloat162float(__low2bfloat16(h0));
                    float ly = v.y - __bfloat162float(__high2bfloat16(h0));
                    float lz = v.z - __bfloat162float(__low2bfloat16(h1));
                    float lw = v.w - __bfloat162float(__high2bfloat16(h1));
                    ((__nv_bfloat162*)(dhi + c4 * 4))[0] = h0;
                    ((__nv_bfloat162*)(dhi + c4 * 4))[1] = h1;
                    ((__nv_bfloat162*)(dlo + c4 * 4))[0] = __floats2bfloat162_rn(lx, ly);
                    ((__nv_bfloat162*)(dlo + c4 * 4))[1] = __floats2bfloat162_rn(lz, lw);
                }
            }
        }
    }
    __syncthreads();

    // ---------------- Phase 2: split-bf16 MMA (validated geometry) ---------
    // 8 warps: b = wid>>2, wm = (wid>>1)&1, wn = wid&1; warp tile 16m x 16n.
    {
        const int wb = wid >> 2;
        const int wm = (wid >> 1) & 1;
        const int wn = wid & 1;

        float acc[2][4];
        #pragma unroll
        for (int j = 0; j < 2; j++)
            #pragma unroll
            for (int k = 0; k < 4; k++) acc[j][k] = 0.f;

        const int paT[3] = {0, 1, 0};   // A part per pass: hi, lo, hi
        const int pbT[3] = {0, 0, 1};   // B part per pass: hi, hi, lo

        #pragma unroll
        for (int pass = 0; pass < 3; pass++) {
            const __nv_bfloat16* Ab = sA + ((wb * 2 + paT[pass]) * MT) * GSTRIDE;
            const __nv_bfloat16* Bb = sB + ((wb * 2 + pbT[pass]) * NT) * GSTRIDE;
            #pragma unroll
            for (int ks = 0; ks < 8; ks++) {
                uint32_t a[4];
                {
                    int r = wm * 16 + ((lane >> 3) & 1) * 8 + (lane & 7);
                    int c = ks * 16 + (lane >> 4) * 8;
                    uint32_t addr = ldsm_addr(Ab + r * GSTRIDE + c);
                    asm volatile("ldmatrix.sync.aligned.m8n8.x4.shared.b16 {%0,%1,%2,%3}, [%4];"
                                 : "=r"(a[0]), "=r"(a[1]), "=r"(a[2]), "=r"(a[3])
                                 : "r"(addr));
                }
                uint32_t bf[4];
                {
                    int r = wn * 16 + ((lane >> 4) & 1) * 8 + (lane & 7);
                    int c = ks * 16 + ((lane >> 3) & 1) * 8;
                    uint32_t addr = ldsm_addr(Bb + r * GSTRIDE + c);
                    asm volatile("ldmatrix.sync.aligned.m8n8.x4.shared.b16 {%0,%1,%2,%3}, [%4];"
                                 : "=r"(bf[0]), "=r"(bf[1]), "=r"(bf[2]), "=r"(bf[3])
                                 : "r"(addr));
                }
                #pragma unroll
                for (int nt = 0; nt < 2; nt++) {
                    asm volatile(
                        "mma.sync.aligned.m16n8k16.row.col.f32.bf16.bf16.f32 "
                        "{%0,%1,%2,%3}, {%4,%5,%6,%7}, {%8,%9}, {%0,%1,%2,%3};"
                        : "+f"(acc[nt][0]), "+f"(acc[nt][1]),
                          "+f"(acc[nt][2]), "+f"(acc[nt][3])
                        : "r"(a[0]), "r"(a[1]), "r"(a[2]), "r"(a[3]),
                          "r"(bf[nt * 2 + 0]), "r"(bf[nt * 2 + 1]));
                }
            }
        }

        // Write G warp tile to smem.
        #pragma unroll
        for (int nt = 0; nt < 2; nt++) {
            int m = wm * 16 + (lane >> 2);
            int n = wn * 16 + nt * 8 + (lane & 3) * 2;
            float* g = sG + (wb * MT + m) * GS + n;
            *(float2*)g            = make_float2(acc[nt][0], acc[nt][1]);
            *(float2*)(g + 8 * GS) = make_float2(acc[nt][2], acc[nt][3]);
        }
    }
    __syncthreads();

    // ---------------- Phase 3: streaming epilogue --------------------------
    {
        const int o4 = tid & 7;
        const int si = tid >> 3;
        const int E4 = E_DIM / 4;                     // 256
        const int sg = s0 + si;
        const int o4g = (o0 >> 2) + o4;

        const float4 g0 = *(const float4*)(sG + (0 * MT + si) * GS + o4 * 4);
        const float4 g1 = *(const float4*)(sG + (1 * MT + si) * GS + o4 * 4);

        const size_t rstep = (size_t)E_DIM * E4;      // R float4 stride per r
        const size_t rbase = (size_t)sg * E4 + o4g;
        const size_t ob0   = ((size_t)sg * R_REL) * E4 + o4g;
        const size_t ob1   = (((size_t)E_DIM + sg) * R_REL) * E4 + o4g;

        #pragma unroll
        for (int rc = 0; rc < R_REL; rc += 8) {
            // Staged prefetch: start the DRAM->L2 fill for chunk rc+8 now;
            // it is consumed ~one chunk later (short distance -> no eviction).
            if (rc + 8 < R_REL) {
                asm volatile("prefetch.global.L2 [%0];"
                             :: "l"(pfbase + ((size_t)(rc + 8) / 8) * pfstride));
            }

            float4 rv[8];
            #pragma unroll
            for (int rr = 0; rr < 8; rr++)
                rv[rr] = __ldcs(&Rrel[(size_t)(rc + rr) * rstep + rbase]);

            #pragma unroll
            for (int rr = 0; rr < 8; rr++) {
                const int r = rc + rr;
                float4 a, c;
                a.x = g0.x * rv[rr].x;  a.y = g0.y * rv[rr].y;
                a.z = g0.z * rv[rr].z;  a.w = g0.w * rv[rr].w;
                c.x = g1.x * rv[rr].x;  c.y = g1.y * rv[rr].y;
                c.z = g1.z * rv[rr].z;  c.w = g1.w * rv[rr].w;
                __stcs(&out[ob0 + (size_t)r * E4], a);
                __stcs(&out[ob1 + (size_t)r * E4], c);
            }
        }
    }
}

extern "C" void kernel_launch(void* const* d_in, const int* in_sizes, int n_in,
                              void* d_out, int out_size) {
    const float* x  = (const float*)d_in[0];   // (B, E, C) fp32
    const float* Rr = (const float*)d_in[1];   // (R_REL, E, E) fp32
    float* out      = (float*)d_out;           // (B, E, R_REL, E) fp32

    cudaFuncSetAttribute(fused_kernel,
                         cudaFuncAttributeMaxDynamicSharedMemorySize, SMEM_BYTES);

    dim3 grid(E_DIM / NT, E_DIM / MT);         // 32 x 32 = 1024 blocks
    fused_kernel<<<grid, 256, SMEM_BYTES>>>(x, (const float4*)Rr, (float4*)out);

    (void)in_sizes; (void)n_in; (void)out_size;
}